// round 2
// baseline (speedup 1.0000x reference)
#include <cuda_runtime.h>

// Bilateral filter 9x9, sigma_s=3, sigma_r=0.1, reflect padding, 4096x4096 fp32.
//
// w = exp2( Ls(dy,dx) - K2*(win-c)^2 ),  K2 = 50*log2(e)
// expanded: arg = (-K2*win + a)*win + (base + Ls),  a = 2*K2*c, base = -K2*c^2
//
// Round-2: 4 pixels/thread, LDS.128 window loads (3 per row per thread),
// division-free tile fill, float4 store. Target: issue-slot reduction.

#define IMG_H 4096
#define IMG_W 4096
#define RAD 4
#define BX 32
#define BY 8
#define PXW 4                    // pixels per thread (horizontal)
#define TILE_PW (BX * PXW)       // 128 pixels wide per block
#define TW (TILE_PW + 2*RAD)     // 136 floats per tile row (544B, 16B-aligned stride)
#define TH (BY + 2*RAD)          // 16 rows

__device__ __forceinline__ float ex2f(float x) {
    float y;
    asm("ex2.approx.f32 %0, %1;" : "=f"(y) : "f"(x));
    return y;
}

__global__ __launch_bounds__(BX * BY)
void bilateral_kernel(const float* __restrict__ img, float* __restrict__ out) {
    __shared__ float tile[TH][TW];

    const int tx = threadIdx.x;
    const int ty = threadIdx.y;
    const int bx0 = blockIdx.x * TILE_PW;
    const int by0 = blockIdx.y * BY;

    // ---- tile fill: warp-per-row strided, no division, reflect at edges ----
    #pragma unroll
    for (int r = ty; r < TH; r += BY) {
        int gy = by0 + r - RAD;
        gy = (gy < 0) ? -gy : ((gy >= IMG_H) ? (2 * IMG_H - 2 - gy) : gy);
        const float* __restrict__ src = img + (size_t)gy * IMG_W;
        #pragma unroll
        for (int c = tx; c < TW; c += BX) {
            int gx = bx0 + c - RAD;
            gx = (gx < 0) ? -gx : ((gx >= IMG_W) ? (2 * IMG_W - 2 - gx) : gx);
            tile[r][c] = src[gx];
        }
    }
    __syncthreads();

    const float K2 = 72.13475204444817f;                    // 50 * log2(e)
    const float LOG2E_OVER_S = 1.4426950408889634f / 18.0f;

    const int cb = tx * PXW;   // window col base within tile (16B aligned)

    // center values for the 4 pixels (tile row ty+RAD, cols cb+4..cb+7)
    const float4 cv = *reinterpret_cast<const float4*>(&tile[ty + RAD][cb + 4]);
    float cc[4] = {cv.x, cv.y, cv.z, cv.w};
    float aa[4], bb[4];
    #pragma unroll
    for (int j = 0; j < 4; j++) {
        aa[j] = 2.0f * K2 * cc[j];
        bb[j] = -K2 * cc[j] * cc[j];
    }

    float num[4] = {0.f, 0.f, 0.f, 0.f};
    float den[4] = {0.f, 0.f, 0.f, 0.f};

    #pragma unroll
    for (int dy = 0; dy < 9; dy++) {
        const float* __restrict__ rp = &tile[ty + dy][cb];
        const float4 v0 = *reinterpret_cast<const float4*>(rp);
        const float4 v1 = *reinterpret_cast<const float4*>(rp + 4);
        const float4 v2 = *reinterpret_cast<const float4*>(rp + 8);
        const float f[12] = {v0.x, v0.y, v0.z, v0.w,
                             v1.x, v1.y, v1.z, v1.w,
                             v2.x, v2.y, v2.z, v2.w};
        #pragma unroll
        for (int j = 0; j < 4; j++) {
            #pragma unroll
            for (int dx = 0; dx < 9; dx++) {
                const float win = f[j + dx];
                // compile-time spatial log2 weight; bb[j]+Ls CSE'd to 15 adds/pixel
                const float Ls = -(float)((dx - 4) * (dx - 4) + (dy - 4) * (dy - 4)) * LOG2E_OVER_S;
                const float btap = bb[j] + Ls;
                const float t   = fmaf(-K2, win, aa[j]);   // FFMA-imm (rt=1)
                const float arg = fmaf(win, t, btap);
                const float w   = ex2f(arg);               // MUFU.EX2
                num[j] = fmaf(w, win, num[j]);
                den[j] += w;
            }
        }
    }

    float4 o;
    o.x = __fdividef(num[0], den[0]);
    o.y = __fdividef(num[1], den[1]);
    o.z = __fdividef(num[2], den[2]);
    o.w = __fdividef(num[3], den[3]);
    *reinterpret_cast<float4*>(&out[(size_t)(by0 + ty) * IMG_W + bx0 + cb]) = o;
}

extern "C" void kernel_launch(void* const* d_in, const int* in_sizes, int n_in,
                              void* d_out, int out_size) {
    const float* img = (const float*)d_in[0];
    float* out = (float*)d_out;
    dim3 block(BX, BY);
    dim3 grid(IMG_W / TILE_PW, IMG_H / BY);
    bilateral_kernel<<<grid, block>>>(img, out);
}

// round 3
// speedup vs baseline: 1.1756x; 1.1756x over previous
#include <cuda_runtime.h>

// Bilateral filter 9x9, sigma_s=3, sigma_r=0.1, reflect padding, 4096x4096 fp32.
//
// w = exp2( Ls(dy,dx) - K2*(win-c)^2 ),  K2 = 50*log2(e)
// expanded: arg = (-K2*win + a)*win + b + Ls,  a = 2*K2*c, b = -K2*c^2
//
// Round-3: 2 pixels/thread (horizontal), packed f32x2 math (FFMA2) for the
// per-tap polynomial and accumulators, LDS.64 window loads shared by the
// pixel pair, spatial term as scalar FADD-immediate. Targets issue slots
// while keeping regs ~50 (occupancy >= ~60%).

#define IMG_H 4096
#define IMG_W 4096
#define RAD 4
#define BX 32
#define BY 8
#define PXW 2
#define TILE_PW (BX * PXW)        // 64 pixels wide per block
#define TW (TILE_PW + 2*RAD)      // 72 floats per tile row (288B, 8B-aligned stride)
#define TH (BY + 2*RAD)           // 16 rows

__device__ __forceinline__ float ex2f(float x) {
    float y;
    asm("ex2.approx.f32 %0, %1;" : "=f"(y) : "f"(x));
    return y;
}

__device__ __forceinline__ float2 fma2(float2 a, float2 b, float2 c) {
    float2 d;
    asm("fma.rn.f32x2 %0, %1, %2, %3;"
        : "=l"(reinterpret_cast<unsigned long long&>(d))
        : "l"(reinterpret_cast<unsigned long long&>(a)),
          "l"(reinterpret_cast<unsigned long long&>(b)),
          "l"(reinterpret_cast<unsigned long long&>(c)));
    return d;
}

__device__ __forceinline__ float2 add2(float2 a, float2 b) {
    float2 d;
    asm("add.rn.f32x2 %0, %1, %2;"
        : "=l"(reinterpret_cast<unsigned long long&>(d))
        : "l"(reinterpret_cast<unsigned long long&>(a)),
          "l"(reinterpret_cast<unsigned long long&>(b)));
    return d;
}

__global__ __launch_bounds__(BX * BY)
void bilateral_kernel(const float* __restrict__ img, float* __restrict__ out) {
    __shared__ __align__(16) float tile[TH][TW];

    const int tx = threadIdx.x;
    const int ty = threadIdx.y;
    const int bx0 = blockIdx.x * TILE_PW;
    const int by0 = blockIdx.y * BY;

    // ---- tile fill: warp-per-row strided, no division, reflect at edges ----
    #pragma unroll
    for (int r = ty; r < TH; r += BY) {
        int gy = by0 + r - RAD;
        gy = (gy < 0) ? -gy : ((gy >= IMG_H) ? (2 * IMG_H - 2 - gy) : gy);
        const float* __restrict__ src = img + (size_t)gy * IMG_W;
        #pragma unroll
        for (int c = tx; c < TW; c += BX) {
            int gx = bx0 + c - RAD;
            gx = (gx < 0) ? -gx : ((gx >= IMG_W) ? (2 * IMG_W - 2 - gx) : gx);
            tile[r][c] = src[gx];
        }
    }
    __syncthreads();

    const float K2 = 72.13475204444817f;                     // 50 * log2(e)
    const float LOG2E_OVER_S = 1.4426950408889634f / 18.0f;

    const int cb = tx * PXW;   // window col base within tile (8B aligned)

    // centers for the 2 pixels: tile[ty+4][cb+4], [cb+5]
    const float c0 = tile[ty + RAD][cb + 4];
    const float c1 = tile[ty + RAD][cb + 5];

    const float2 nK2_2 = make_float2(-K2, -K2);
    const float2 a2    = make_float2(2.0f * K2 * c0, 2.0f * K2 * c1);
    const float2 b2    = make_float2(-K2 * c0 * c0, -K2 * c1 * c1);

    float2 num2 = make_float2(0.f, 0.f);
    float2 den2 = make_float2(0.f, 0.f);

    #pragma unroll
    for (int dy = 0; dy < 9; dy++) {
        // union window for the pixel pair spans 10 floats -> 5 LDS.64
        const float2* __restrict__ rp =
            reinterpret_cast<const float2*>(&tile[ty + dy][cb]);
        float2 p0 = rp[0], p1 = rp[1], p2 = rp[2], p3 = rp[3], p4 = rp[4];
        const float f[10] = {p0.x, p0.y, p1.x, p1.y, p2.x,
                             p2.y, p3.x, p3.y, p4.x, p4.y};

        #pragma unroll
        for (int k = 0; k < 9; k++) {
            // pixel0 tap value f[k], pixel1 tap value f[k+1]
            float2 win2 = make_float2(f[k], f[k + 1]);

            // packed polynomial: g = (-K2*win + a)*win + b   (both pixels)
            float2 t2 = fma2(nK2_2, win2, a2);
            float2 g2 = fma2(win2, t2, b2);

            // spatial log2-weight, compile-time constant, scalar FADD-imm
            const float Ls = -(float)((k - 4) * (k - 4) + (dy - 4) * (dy - 4))
                             * LOG2E_OVER_S;
            float w0 = ex2f(g2.x + Ls);
            float w1 = ex2f(g2.y + Ls);
            float2 w2 = make_float2(w0, w1);

            num2 = fma2(w2, win2, num2);
            den2 = add2(den2, w2);
        }
    }

    float2 o;
    o.x = __fdividef(num2.x, den2.x);
    o.y = __fdividef(num2.y, den2.y);
    *reinterpret_cast<float2*>(&out[(size_t)(by0 + ty) * IMG_W + bx0 + cb]) = o;
}

extern "C" void kernel_launch(void* const* d_in, const int* in_sizes, int n_in,
                              void* d_out, int out_size) {
    const float* img = (const float*)d_in[0];
    float* out = (float*)d_out;
    dim3 block(BX, BY);
    dim3 grid(IMG_W / TILE_PW, IMG_H / BY);
    bilateral_kernel<<<grid, block>>>(img, out);
}